// round 16
// baseline (speedup 1.0000x reference)
#include <cuda_runtime.h>
#include <cuda_bf16.h>
#include <cuda_fp16.h>
#include <cstdint>

#define NN 131072
#define EE 2097152

// ---------------- device scratch (static; no allocation allowed) ----------------
__device__ float2 g_dc[NN];            // (deg accumulator, count accumulator)
__device__ float  g_dis[NN];           // rsqrt(deg)
__device__ int    g_cnt[NN];           // int count
__device__ int    g_rowptr[NN];        // CSR row start (arbitrary disjoint alloc)
__device__ int    g_cur[NN];           // scatter cursor
__device__ int    g_alloc;             // global CSR allocation cursor
__device__ int2   g_csr[EE];           // (src, __float_as_int(dis[s]*w)), grouped by dst
__device__ __half g_aggh[NN * 64];     // A_norm @ x        (fp16)
__device__ __half g_h2h[NN * 64];      // relu(agg@W1+b1)@W2 (fp16)
__device__ __half g_h3h[NN * 64];      // A_norm @ h2t       (fp16, for FC)

// ---------------- init ----------------
__global__ void k_init() {
    int i = blockIdx.x * blockDim.x + threadIdx.x;
    if (i < NN) g_dc[i] = make_float2(1.0f, 0.0f);   // self-loop weight = 1
    if (i == 0) g_alloc = 0;
}

// ---------------- degree + histogram: ONE vector reduction per edge ----------------
__global__ void k_deg_hist(const int* __restrict__ ei, const float* __restrict__ ew) {
    int e = blockIdx.x * blockDim.x + threadIdx.x;
    if (e < EE) {
        int d = ei[EE + e];
        float w = ew[e];
        asm volatile("red.global.add.v2.f32 [%0], {%1,%2};"
                     :: "l"(&g_dc[d]), "f"(w), "f"(1.0f) : "memory");
    }
}

// ---------------- row allocation: warp-aggregated bump allocator -------------------
// CSR row ranges need only be disjoint+contiguous per node, NOT ordered by node id.
__global__ void k_rowalloc() {
    int i = blockIdx.x * 256 + threadIdx.x;
    int lane = threadIdx.x & 31;
    float2 dc = g_dc[i];
    int c = (int)dc.y;
    // inclusive warp scan of c
    int p = c;
    #pragma unroll
    for (int off = 1; off < 32; off <<= 1) {
        int u = __shfl_up_sync(0xffffffffu, p, off);
        if (lane >= off) p += u;
    }
    int total = __shfl_sync(0xffffffffu, p, 31);
    int base = 0;
    if (lane == 31) base = atomicAdd(&g_alloc, total);
    base = __shfl_sync(0xffffffffu, base, 31);
    int pos = base + p - c;                 // exclusive within warp
    g_rowptr[i] = pos;
    g_cur[i] = pos;
    g_dis[i] = rsqrtf(dc.x);                // deg >= 1 (self-loop)
    g_cnt[i] = c;
}

// ---------------- scatter: 2 edges/thread, payload = dis[s]*w ----------------------
__global__ void k_scatter(const int* __restrict__ ei, const float* __restrict__ ew) {
    int e = (blockIdx.x * 256 + threadIdx.x) * 2;
    if (e >= EE) return;
    int2 ss = *(const int2*)&ei[e];
    int2 dd = *(const int2*)&ei[EE + e];
    float2 ww = *(const float2*)&ew[e];
    float p0 = g_dis[ss.x] * ww.x;
    float p1 = g_dis[ss.y] * ww.y;
    int pos0 = atomicAdd(&g_cur[dd.x], 1);
    g_csr[pos0] = make_int2(ss.x, __float_as_int(p0));
    int pos1 = atomicAdd(&g_cur[dd.y], 1);
    g_csr[pos1] = make_int2(ss.y, __float_as_int(p1));
}

// ---------------- CSR gather aggregation: one warp/node, MLP=4, fp16 out -----------
// out[d] = dis[d] * ( dis[d]*x[d] + sum_e p_e * x[src_e] )
template<bool IN_HALF>
__global__ void k_agg(const void* __restrict__ Xv, __half* __restrict__ Out) {
    int warp = threadIdx.x >> 5;
    int lane = threadIdx.x & 31;
    int node = blockIdx.x * 8 + warp;

    auto ldrow = [&](int row) -> float2 {
        if (IN_HALF) return __half22float2(((const __half2*)Xv)[row * 32 + lane]);
        else         return ((const float2*)Xv)[row * 32 + lane];
    };

    float dn = g_dis[node];
    float2 xs = ldrow(node);
    float2 acc0 = make_float2(dn * xs.x, dn * xs.y);
    float2 acc1 = make_float2(0.f, 0.f);
    float2 acc2 = make_float2(0.f, 0.f);
    float2 acc3 = make_float2(0.f, 0.f);

    int beg = g_rowptr[node];
    int deg = g_cnt[node];

    for (int base = 0; base < deg; base += 32) {
        int n = min(32, deg - base);
        int2 entry = make_int2(0, 0);
        if (lane < n) entry = g_csr[beg + base + lane];   // coalesced
        int j = 0;
        for (; j + 4 <= n; j += 4) {
            int s0 = __shfl_sync(0xffffffffu, entry.x, j);
            int w0 = __shfl_sync(0xffffffffu, entry.y, j);
            int s1 = __shfl_sync(0xffffffffu, entry.x, j + 1);
            int w1 = __shfl_sync(0xffffffffu, entry.y, j + 1);
            int s2 = __shfl_sync(0xffffffffu, entry.x, j + 2);
            int w2 = __shfl_sync(0xffffffffu, entry.y, j + 2);
            int s3 = __shfl_sync(0xffffffffu, entry.x, j + 3);
            int w3 = __shfl_sync(0xffffffffu, entry.y, j + 3);
            float2 v0 = ldrow(s0);                        // 4 gathers in flight
            float2 v1 = ldrow(s1);
            float2 v2 = ldrow(s2);
            float2 v3 = ldrow(s3);
            float n0 = __int_as_float(w0);
            float n1 = __int_as_float(w1);
            float n2 = __int_as_float(w2);
            float n3 = __int_as_float(w3);
            acc0.x = fmaf(n0, v0.x, acc0.x); acc0.y = fmaf(n0, v0.y, acc0.y);
            acc1.x = fmaf(n1, v1.x, acc1.x); acc1.y = fmaf(n1, v1.y, acc1.y);
            acc2.x = fmaf(n2, v2.x, acc2.x); acc2.y = fmaf(n2, v2.y, acc2.y);
            acc3.x = fmaf(n3, v3.x, acc3.x); acc3.y = fmaf(n3, v3.y, acc3.y);
        }
        for (; j < n; j++) {
            int s0 = __shfl_sync(0xffffffffu, entry.x, j);
            int w0 = __shfl_sync(0xffffffffu, entry.y, j);
            float2 v0 = ldrow(s0);
            float n0 = __int_as_float(w0);
            acc0.x = fmaf(n0, v0.x, acc0.x);
            acc0.y = fmaf(n0, v0.y, acc0.y);
        }
    }
    float ox = dn * ((acc0.x + acc1.x) + (acc2.x + acc3.x));
    float oy = dn * ((acc0.y + acc1.y) + (acc2.y + acc3.y));
    ((__half2*)Out)[node * 32 + lane] = __floats2half2_rn(ox, oy);
}

// ---------------- tf32 helpers ----------------
__device__ __forceinline__ unsigned int cvt_tf32(float f) {
    unsigned int o;
    asm("cvt.rna.tf32.f32 %0, %1;" : "=r"(o) : "f"(f));
    return o;
}

__device__ __forceinline__ void mma_tf32(float* c, unsigned int a0, unsigned int a1,
                                         unsigned int a2, unsigned int a3,
                                         unsigned int b0, unsigned int b1) {
    asm volatile("mma.sync.aligned.m16n8k8.row.col.f32.tf32.tf32.f32 "
                 "{%0,%1,%2,%3}, {%4,%5,%6,%7}, {%8,%9}, {%0,%1,%2,%3};"
                 : "+f"(c[0]), "+f"(c[1]), "+f"(c[2]), "+f"(c[3])
                 : "r"(a0), "r"(a1), "r"(a2), "r"(a3), "r"(b0), "r"(b1));
}

// ---------------- fused double GEMM: h2h = (relu(X@W1+b1)) @ W2, fp16 in/out --------
__global__ void gemm12(const __half* __restrict__ X, const float* __restrict__ W1,
                       const float* __restrict__ b1, const float* __restrict__ W2,
                       __half* __restrict__ Yh) {
    extern __shared__ float smem[];
    float* sX  = smem;            // 128 x 68
    float* sW1 = smem + 8704;     // 64 x 136
    float* sW2 = smem + 17408;    // 128 x 72
    float* sT1 = smem;            // 128 x 132 (aliases sX/sW1 after stage 1)

    int tid = threadIdx.x, lane = tid & 31, warp = tid >> 5;
    int row0 = blockIdx.x * 128;

    const uint2* Xu = (const uint2*)X;
    #pragma unroll 4
    for (int idx = tid; idx < 128 * 16; idx += 256) {
        int r = idx >> 4, c = idx & 15;
        uint2 u = Xu[(size_t)(row0 + r) * 16 + c];
        float2 f0 = __half22float2(*(__half2*)&u.x);
        float2 f1 = __half22float2(*(__half2*)&u.y);
        float* dst = &sX[r * 68 + c * 4];
        dst[0] = f0.x; dst[1] = f0.y; dst[2] = f1.x; dst[3] = f1.y;
    }
    #pragma unroll 4
    for (int idx = tid; idx < 64 * 32; idx += 256) {           // W1 64x128
        int r = idx / 32, c4 = idx % 32;
        float4 v = ((const float4*)(W1 + r * 128))[c4];
        *(float4*)&sW1[r * 136 + c4 * 4] = v;
    }
    #pragma unroll 4
    for (int idx = tid; idx < 128 * 16; idx += 256) {          // W2 128x64
        int r = idx / 16, c4 = idx % 16;
        float4 v = ((const float4*)(W2 + r * 64))[c4];
        *(float4*)&sW2[r * 72 + c4 * 4] = v;
    }
    __syncthreads();

    int ar = warp * 16 + (lane >> 2);
    int ak = lane & 3;
    int bk = lane & 3;
    int bn = lane >> 2;

    // ---- stage 1: acc1 = X @ W1 ----
    float acc1[16][4];
    #pragma unroll
    for (int t = 0; t < 16; t++)
        #pragma unroll
        for (int i = 0; i < 4; i++) acc1[t][i] = 0.0f;

    #pragma unroll
    for (int ks = 0; ks < 8; ks++) {
        int k0 = ks * 8;
        unsigned int a0 = cvt_tf32(sX[ar * 68 + k0 + ak]);
        unsigned int a1 = cvt_tf32(sX[(ar + 8) * 68 + k0 + ak]);
        unsigned int a2 = cvt_tf32(sX[ar * 68 + k0 + ak + 4]);
        unsigned int a3 = cvt_tf32(sX[(ar + 8) * 68 + k0 + ak + 4]);
        #pragma unroll
        for (int t = 0; t < 16; t++) {
            unsigned int b0 = cvt_tf32(sW1[(k0 + bk) * 136 + t * 8 + bn]);
            unsigned int b1 = cvt_tf32(sW1[(k0 + bk + 4) * 136 + t * 8 + bn]);
            mma_tf32(acc1[t], a0, a1, a2, a3, b0, b1);
        }
    }
    __syncthreads();

    // ---- T1 = relu(acc1 + b1) -> sT1 ----
    #pragma unroll
    for (int t = 0; t < 16; t++) {
        int col = t * 8 + 2 * (lane & 3);
        float bb0 = b1[col], bb1 = b1[col + 1];
        sT1[ar * 132 + col]           = fmaxf(acc1[t][0] + bb0, 0.f);
        sT1[ar * 132 + col + 1]       = fmaxf(acc1[t][1] + bb1, 0.f);
        sT1[(ar + 8) * 132 + col]     = fmaxf(acc1[t][2] + bb0, 0.f);
        sT1[(ar + 8) * 132 + col + 1] = fmaxf(acc1[t][3] + bb1, 0.f);
    }
    __syncthreads();

    // ---- stage 2: acc2 = T1 @ W2 ----
    float acc2[8][4];
    #pragma unroll
    for (int t = 0; t < 8; t++)
        #pragma unroll
        for (int i = 0; i < 4; i++) acc2[t][i] = 0.0f;

    #pragma unroll
    for (int ks = 0; ks < 16; ks++) {
        int k0 = ks * 8;
        unsigned int a0 = cvt_tf32(sT1[ar * 132 + k0 + ak]);
        unsigned int a1 = cvt_tf32(sT1[(ar + 8) * 132 + k0 + ak]);
        unsigned int a2 = cvt_tf32(sT1[ar * 132 + k0 + ak + 4]);
        unsigned int a3 = cvt_tf32(sT1[(ar + 8) * 132 + k0 + ak + 4]);
        #pragma unroll
        for (int t = 0; t < 8; t++) {
            unsigned int b0 = cvt_tf32(sW2[(k0 + bk) * 72 + t * 8 + bn]);
            unsigned int b1 = cvt_tf32(sW2[(k0 + bk + 4) * 72 + t * 8 + bn]);
            mma_tf32(acc2[t], a0, a1, a2, a3, b0, b1);
        }
    }

    // ---- epilogue: fp16 out ----
    int orow = row0 + ar;
    __half2* Y2 = (__half2*)Yh;
    #pragma unroll
    for (int t = 0; t < 8; t++) {
        int col = t * 8 + 2 * (lane & 3);
        Y2[((size_t)orow * 64 + col) / 2]       = __floats2half2_rn(acc2[t][0], acc2[t][1]);
        Y2[((size_t)(orow + 8) * 64 + col) / 2] = __floats2half2_rn(acc2[t][2], acc2[t][3]);
    }
}

// ---------------- FC + softmax, 8 graphs per block (Wfc register reuse) -------------
__global__ void fc_softmax8(const __half* __restrict__ H, const float* __restrict__ Wfc,
                            const float* __restrict__ bfc, const float* __restrict__ b2,
                            float* __restrict__ out) {
    int g0 = blockIdx.x * 8;                  // 128 blocks
    int tid = threadIdx.x;                    // 256
    int lane = tid & 31, warp = tid >> 5;

    __shared__ float s_b2[64];
    if (tid < 64) s_b2[tid] = b2[tid];
    __syncthreads();

    float acc[8][4];
    #pragma unroll
    for (int gi = 0; gi < 8; gi++)
        #pragma unroll
        for (int c = 0; c < 4; c++) acc[gi][c] = 0.0f;

    #pragma unroll 2
    for (int k = 0; k < 8; k++) {
        int j = (k * 256 + tid) * 4;          // element 0..8191, step 4
        float4 w0 = __ldg((const float4*)Wfc + j);
        float4 w1 = __ldg((const float4*)Wfc + j + 1);
        float4 w2 = __ldg((const float4*)Wfc + j + 2);
        float4 w3 = __ldg((const float4*)Wfc + j + 3);
        int jb = j & 63;
        float bb0 = s_b2[jb], bb1 = s_b2[jb + 1], bb2 = s_b2[jb + 2], bb3 = s_b2[jb + 3];
        #pragma unroll
        for (int gi = 0; gi < 8; gi++) {
            const __half2* hp = (const __half2*)(H + (size_t)(g0 + gi) * 8192 + j);
            float2 h0 = __half22float2(hp[0]);
            float2 h1 = __half22float2(hp[1]);
            float v0 = fmaxf(h0.x + bb0, 0.f);
            float v1 = fmaxf(h0.y + bb1, 0.f);
            float v2 = fmaxf(h1.x + bb2, 0.f);
            float v3 = fmaxf(h1.y + bb3, 0.f);
            acc[gi][0] = fmaf(v0, w0.x, fmaf(v1, w1.x, fmaf(v2, w2.x, fmaf(v3, w3.x, acc[gi][0]))));
            acc[gi][1] = fmaf(v0, w0.y, fmaf(v1, w1.y, fmaf(v2, w2.y, fmaf(v3, w3.y, acc[gi][1]))));
            acc[gi][2] = fmaf(v0, w0.z, fmaf(v1, w1.z, fmaf(v2, w2.z, fmaf(v3, w3.z, acc[gi][2]))));
            acc[gi][3] = fmaf(v0, w0.w, fmaf(v1, w1.w, fmaf(v2, w2.w, fmaf(v3, w3.w, acc[gi][3]))));
        }
    }

    __shared__ float sred[8][8][4];           // warp, graph, class
    #pragma unroll
    for (int gi = 0; gi < 8; gi++) {
        float a0 = acc[gi][0], a1 = acc[gi][1], a2 = acc[gi][2], a3 = acc[gi][3];
        #pragma unroll
        for (int off = 16; off > 0; off >>= 1) {
            a0 += __shfl_xor_sync(0xffffffffu, a0, off);
            a1 += __shfl_xor_sync(0xffffffffu, a1, off);
            a2 += __shfl_xor_sync(0xffffffffu, a2, off);
            a3 += __shfl_xor_sync(0xffffffffu, a3, off);
        }
        if (lane == 0) {
            sred[warp][gi][0] = a0; sred[warp][gi][1] = a1;
            sred[warp][gi][2] = a2; sred[warp][gi][3] = a3;
        }
    }
    __syncthreads();
    if (tid < 8) {
        float l[4];
        #pragma unroll
        for (int c = 0; c < 4; c++) {
            float s = bfc[c];
            #pragma unroll
            for (int w = 0; w < 8; w++) s += sred[w][tid][c];
            l[c] = s;
        }
        float m = fmaxf(fmaxf(l[0], l[1]), fmaxf(l[2], l[3]));
        float e0 = __expf(l[0] - m), e1 = __expf(l[1] - m);
        float e2 = __expf(l[2] - m), e3 = __expf(l[3] - m);
        float inv = 1.0f / (e0 + e1 + e2 + e3);
        float* o = out + (size_t)(g0 + tid) * 4;
        o[0] = e0 * inv; o[1] = e1 * inv; o[2] = e2 * inv; o[3] = e3 * inv;
    }
}

// ---------------- launch ----------------
extern "C" void kernel_launch(void* const* d_in, const int* in_sizes, int n_in,
                              void* d_out, int out_size) {
    const float* x   = (const float*)d_in[0];
    const int*   ei  = (const int*)d_in[1];
    const float* ew  = (const float*)d_in[2];
    const float* W1  = (const float*)d_in[3];
    const float* b1  = (const float*)d_in[4];
    const float* W2  = (const float*)d_in[5];
    const float* b2  = (const float*)d_in[6];
    const float* Wfc = (const float*)d_in[7];
    const float* bfc = (const float*)d_in[8];
    float* out = (float*)d_out;

    __half* aggh; cudaGetSymbolAddress((void**)&aggh, g_aggh);
    __half* h2h;  cudaGetSymbolAddress((void**)&h2h, g_h2h);
    __half* h3h;  cudaGetSymbolAddress((void**)&h3h, g_h3h);

    const int smem12 = 26624 * 4;   // 104 KB
    cudaFuncSetAttribute(gemm12, cudaFuncAttributeMaxDynamicSharedMemorySize, smem12);

    // CSR build — single-kernel row allocation replaces the 2-stage scan
    k_init<<<NN / 256, 256>>>();                   // 0
    k_deg_hist<<<EE / 256, 256>>>(ei, ew);         // 1
    k_rowalloc<<<NN / 256, 256>>>();               // 2
    k_scatter<<<EE / 512, 256>>>(ei, ew);          // 3  <- profiled next round

    // layer 1 aggregate (fp32 gathers from x, fp16 out) -> fused double GEMM
    k_agg<false><<<NN / 8, 256>>>(x, aggh);        // 4
    gemm12<<<NN / 128, 256, smem12>>>(aggh, W1, b1, W2, h2h);   // 5

    // layer 2 aggregate (fp16 in/out), then batched FC + softmax
    k_agg<true><<<NN / 8, 256>>>(h2h, h3h);        // 6
    fc_softmax8<<<128, 256>>>(h3h, Wfc, bfc, b2, out);          // 7
}

// round 17
// speedup vs baseline: 1.1002x; 1.1002x over previous
#include <cuda_runtime.h>
#include <cuda_bf16.h>
#include <cuda_fp16.h>
#include <cstdint>

#define NN 131072
#define EE 2097152

// ---------------- device scratch (static; no allocation allowed) ----------------
__device__ float2 g_dc[NN];            // (deg accumulator, count accumulator)
__device__ float  g_dis[NN];           // rsqrt(deg)
__device__ int    g_cnt[NN];           // int count
__device__ int    g_rowptr[NN];        // CSR row start (disjoint bump alloc)
__device__ int    g_cur[NN];           // scatter cursor
__device__ int    g_alloc;             // global CSR allocation cursor
__device__ int2   g_csr[EE];           // (src, __float_as_int(dis[s]*w)), grouped by dst
__device__ __half g_aggh[NN * 64];     // A_norm @ x        (fp16)
__device__ __half g_h2h[NN * 64];      // relu(agg@W1+b1)@W2 (fp16)
__device__ __half g_h3h[NN * 64];      // A_norm @ h2t       (fp16, for FC)

// ---------------- init ----------------
__global__ void k_init() {
    int i = blockIdx.x * blockDim.x + threadIdx.x;
    if (i < NN) g_dc[i] = make_float2(1.0f, 0.0f);   // self-loop weight = 1
    if (i == 0) g_alloc = 0;
}

// ---------------- degree + histogram: ONE vector reduction per edge ----------------
__global__ void k_deg_hist(const int* __restrict__ ei, const float* __restrict__ ew) {
    int e = blockIdx.x * blockDim.x + threadIdx.x;
    if (e < EE) {
        int d = ei[EE + e];
        float w = ew[e];
        asm volatile("red.global.add.v2.f32 [%0], {%1,%2};"
                     :: "l"(&g_dc[d]), "f"(w), "f"(1.0f) : "memory");
    }
}

// ---------------- row allocation: warp-aggregated bump allocator -------------------
// CSR row ranges need only be disjoint+contiguous per node, NOT ordered by node id.
__global__ void k_rowalloc() {
    int i = blockIdx.x * 256 + threadIdx.x;
    int lane = threadIdx.x & 31;
    float2 dc = g_dc[i];
    int c = (int)dc.y;
    int p = c;
    #pragma unroll
    for (int off = 1; off < 32; off <<= 1) {
        int u = __shfl_up_sync(0xffffffffu, p, off);
        if (lane >= off) p += u;
    }
    int total = __shfl_sync(0xffffffffu, p, 31);
    int base = 0;
    if (lane == 31) base = atomicAdd(&g_alloc, total);
    base = __shfl_sync(0xffffffffu, base, 31);
    int pos = base + p - c;
    g_rowptr[i] = pos;
    g_cur[i] = pos;
    g_dis[i] = rsqrtf(dc.x);                // deg >= 1 (self-loop)
    g_cnt[i] = c;
}

// ---------------- scatter: 1 edge/thread (max atomic parallelism) -------------------
__global__ void k_scatter(const int* __restrict__ ei, const float* __restrict__ ew) {
    int e = blockIdx.x * blockDim.x + threadIdx.x;
    if (e >= EE) return;
    int s = ei[e], d = ei[EE + e];
    float p = g_dis[s] * ew[e];
    int pos = atomicAdd(&g_cur[d], 1);
    g_csr[pos] = make_int2(s, __float_as_int(p));
}

// ---------------- CSR gather aggregation: one warp/node, fp16 out (R14 form) --------
// out[d] = dis[d] * ( dis[d]*x[d] + sum_e p_e * x[src_e] )
template<bool IN_HALF>
__global__ void k_agg(const void* __restrict__ Xv, __half* __restrict__ Out) {
    int warp = threadIdx.x >> 5;
    int lane = threadIdx.x & 31;
    int node = blockIdx.x * 8 + warp;

    auto ldrow = [&](int row) -> float2 {
        if (IN_HALF) return __half22float2(((const __half2*)Xv)[row * 32 + lane]);
        else         return ((const float2*)Xv)[row * 32 + lane];
    };

    float dn = g_dis[node];
    float2 xs = ldrow(node);
    float2 acc0 = make_float2(dn * xs.x, dn * xs.y);
    float2 acc1 = make_float2(0.f, 0.f);

    int beg = g_rowptr[node];
    int deg = g_cnt[node];

    for (int base = 0; base < deg; base += 32) {
        int n = min(32, deg - base);
        int2 entry = make_int2(0, 0);
        if (lane < n) entry = g_csr[beg + base + lane];   // coalesced
        int j = 0;
        #pragma unroll 2
        for (; j + 2 <= n; j += 2) {
            int s0 = __shfl_sync(0xffffffffu, entry.x, j);
            int b0 = __shfl_sync(0xffffffffu, entry.y, j);
            int s1 = __shfl_sync(0xffffffffu, entry.x, j + 1);
            int b1 = __shfl_sync(0xffffffffu, entry.y, j + 1);
            float2 v0 = ldrow(s0);
            float2 v1 = ldrow(s1);
            float n0 = __int_as_float(b0);
            float n1 = __int_as_float(b1);
            acc0.x = fmaf(n0, v0.x, acc0.x);
            acc0.y = fmaf(n0, v0.y, acc0.y);
            acc1.x = fmaf(n1, v1.x, acc1.x);
            acc1.y = fmaf(n1, v1.y, acc1.y);
        }
        if (j < n) {
            int s0 = __shfl_sync(0xffffffffu, entry.x, j);
            int b0 = __shfl_sync(0xffffffffu, entry.y, j);
            float2 v0 = ldrow(s0);
            float n0 = __int_as_float(b0);
            acc0.x = fmaf(n0, v0.x, acc0.x);
            acc0.y = fmaf(n0, v0.y, acc0.y);
        }
    }
    float ox = dn * (acc0.x + acc1.x);
    float oy = dn * (acc0.y + acc1.y);
    ((__half2*)Out)[node * 32 + lane] = __floats2half2_rn(ox, oy);
}

// ---------------- tf32 helpers ----------------
__device__ __forceinline__ unsigned int cvt_tf32(float f) {
    unsigned int o;
    asm("cvt.rna.tf32.f32 %0, %1;" : "=r"(o) : "f"(f));
    return o;
}

__device__ __forceinline__ void mma_tf32(float* c, unsigned int a0, unsigned int a1,
                                         unsigned int a2, unsigned int a3,
                                         unsigned int b0, unsigned int b1) {
    asm volatile("mma.sync.aligned.m16n8k8.row.col.f32.tf32.tf32.f32 "
                 "{%0,%1,%2,%3}, {%4,%5,%6,%7}, {%8,%9}, {%0,%1,%2,%3};"
                 : "+f"(c[0]), "+f"(c[1]), "+f"(c[2]), "+f"(c[3])
                 : "r"(a0), "r"(a1), "r"(a2), "r"(a3), "r"(b0), "r"(b1));
}

// ---------------- fused double GEMM: h2h = (relu(X@W1+b1)) @ W2, fp16 in/out --------
__global__ void gemm12(const __half* __restrict__ X, const float* __restrict__ W1,
                       const float* __restrict__ b1, const float* __restrict__ W2,
                       __half* __restrict__ Yh) {
    extern __shared__ float smem[];
    float* sX  = smem;            // 128 x 68
    float* sW1 = smem + 8704;     // 64 x 136
    float* sW2 = smem + 17408;    // 128 x 72
    float* sT1 = smem;            // 128 x 132 (aliases sX/sW1 after stage 1)

    int tid = threadIdx.x, lane = tid & 31, warp = tid >> 5;
    int row0 = blockIdx.x * 128;

    const uint2* Xu = (const uint2*)X;
    #pragma unroll 4
    for (int idx = tid; idx < 128 * 16; idx += 256) {
        int r = idx >> 4, c = idx & 15;
        uint2 u = Xu[(size_t)(row0 + r) * 16 + c];
        float2 f0 = __half22float2(*(__half2*)&u.x);
        float2 f1 = __half22float2(*(__half2*)&u.y);
        float* dst = &sX[r * 68 + c * 4];
        dst[0] = f0.x; dst[1] = f0.y; dst[2] = f1.x; dst[3] = f1.y;
    }
    #pragma unroll 4
    for (int idx = tid; idx < 64 * 32; idx += 256) {           // W1 64x128
        int r = idx / 32, c4 = idx % 32;
        float4 v = ((const float4*)(W1 + r * 128))[c4];
        *(float4*)&sW1[r * 136 + c4 * 4] = v;
    }
    #pragma unroll 4
    for (int idx = tid; idx < 128 * 16; idx += 256) {          // W2 128x64
        int r = idx / 16, c4 = idx % 16;
        float4 v = ((const float4*)(W2 + r * 64))[c4];
        *(float4*)&sW2[r * 72 + c4 * 4] = v;
    }
    __syncthreads();

    int ar = warp * 16 + (lane >> 2);
    int ak = lane & 3;
    int bk = lane & 3;
    int bn = lane >> 2;

    // ---- stage 1: acc1 = X @ W1 ----
    float acc1[16][4];
    #pragma unroll
    for (int t = 0; t < 16; t++)
        #pragma unroll
        for (int i = 0; i < 4; i++) acc1[t][i] = 0.0f;

    #pragma unroll
    for (int ks = 0; ks < 8; ks++) {
        int k0 = ks * 8;
        unsigned int a0 = cvt_tf32(sX[ar * 68 + k0 + ak]);
        unsigned int a1 = cvt_tf32(sX[(ar + 8) * 68 + k0 + ak]);
        unsigned int a2 = cvt_tf32(sX[ar * 68 + k0 + ak + 4]);
        unsigned int a3 = cvt_tf32(sX[(ar + 8) * 68 + k0 + ak + 4]);
        #pragma unroll
        for (int t = 0; t < 16; t++) {
            unsigned int b0 = cvt_tf32(sW1[(k0 + bk) * 136 + t * 8 + bn]);
            unsigned int b1 = cvt_tf32(sW1[(k0 + bk + 4) * 136 + t * 8 + bn]);
            mma_tf32(acc1[t], a0, a1, a2, a3, b0, b1);
        }
    }
    __syncthreads();

    // ---- T1 = relu(acc1 + b1) -> sT1 ----
    #pragma unroll
    for (int t = 0; t < 16; t++) {
        int col = t * 8 + 2 * (lane & 3);
        float bb0 = b1[col], bb1 = b1[col + 1];
        sT1[ar * 132 + col]           = fmaxf(acc1[t][0] + bb0, 0.f);
        sT1[ar * 132 + col + 1]       = fmaxf(acc1[t][1] + bb1, 0.f);
        sT1[(ar + 8) * 132 + col]     = fmaxf(acc1[t][2] + bb0, 0.f);
        sT1[(ar + 8) * 132 + col + 1] = fmaxf(acc1[t][3] + bb1, 0.f);
    }
    __syncthreads();

    // ---- stage 2: acc2 = T1 @ W2 ----
    float acc2[8][4];
    #pragma unroll
    for (int t = 0; t < 8; t++)
        #pragma unroll
        for (int i = 0; i < 4; i++) acc2[t][i] = 0.0f;

    #pragma unroll
    for (int ks = 0; ks < 16; ks++) {
        int k0 = ks * 8;
        unsigned int a0 = cvt_tf32(sT1[ar * 132 + k0 + ak]);
        unsigned int a1 = cvt_tf32(sT1[(ar + 8) * 132 + k0 + ak]);
        unsigned int a2 = cvt_tf32(sT1[ar * 132 + k0 + ak + 4]);
        unsigned int a3 = cvt_tf32(sT1[(ar + 8) * 132 + k0 + ak + 4]);
        #pragma unroll
        for (int t = 0; t < 8; t++) {
            unsigned int b0 = cvt_tf32(sW2[(k0 + bk) * 72 + t * 8 + bn]);
            unsigned int b1 = cvt_tf32(sW2[(k0 + bk + 4) * 72 + t * 8 + bn]);
            mma_tf32(acc2[t], a0, a1, a2, a3, b0, b1);
        }
    }

    // ---- epilogue: fp16 out ----
    int orow = row0 + ar;
    __half2* Y2 = (__half2*)Yh;
    #pragma unroll
    for (int t = 0; t < 8; t++) {
        int col = t * 8 + 2 * (lane & 3);
        Y2[((size_t)orow * 64 + col) / 2]       = __floats2half2_rn(acc2[t][0], acc2[t][1]);
        Y2[((size_t)(orow + 8) * 64 + col) / 2] = __floats2half2_rn(acc2[t][2], acc2[t][3]);
    }
}

// ---------------- FC + softmax, 8 graphs per block (Wfc register reuse) -------------
__global__ void fc_softmax8(const __half* __restrict__ H, const float* __restrict__ Wfc,
                            const float* __restrict__ bfc, const float* __restrict__ b2,
                            float* __restrict__ out) {
    int g0 = blockIdx.x * 8;                  // 128 blocks
    int tid = threadIdx.x;                    // 256
    int lane = tid & 31, warp = tid >> 5;

    __shared__ float s_b2[64];
    if (tid < 64) s_b2[tid] = b2[tid];
    __syncthreads();

    float acc[8][4];
    #pragma unroll
    for (int gi = 0; gi < 8; gi++)
        #pragma unroll
        for (int c = 0; c < 4; c++) acc[gi][c] = 0.0f;

    #pragma unroll 2
    for (int k = 0; k < 8; k++) {
        int j = (k * 256 + tid) * 4;          // element 0..8191, step 4
        float4 w0 = __ldg((const float4*)Wfc + j);
        float4 w1 = __ldg((const float4*)Wfc + j + 1);
        float4 w2 = __ldg((const float4*)Wfc + j + 2);
        float4 w3 = __ldg((const float4*)Wfc + j + 3);
        int jb = j & 63;
        float bb0 = s_b2[jb], bb1 = s_b2[jb + 1], bb2 = s_b2[jb + 2], bb3 = s_b2[jb + 3];
        #pragma unroll
        for (int gi = 0; gi < 8; gi++) {
            const __half2* hp = (const __half2*)(H + (size_t)(g0 + gi) * 8192 + j);
            float2 h0 = __half22float2(hp[0]);
            float2 h1 = __half22float2(hp[1]);
            float v0 = fmaxf(h0.x + bb0, 0.f);
            float v1 = fmaxf(h0.y + bb1, 0.f);
            float v2 = fmaxf(h1.x + bb2, 0.f);
            float v3 = fmaxf(h1.y + bb3, 0.f);
            acc[gi][0] = fmaf(v0, w0.x, fmaf(v1, w1.x, fmaf(v2, w2.x, fmaf(v3, w3.x, acc[gi][0]))));
            acc[gi][1] = fmaf(v0, w0.y, fmaf(v1, w1.y, fmaf(v2, w2.y, fmaf(v3, w3.y, acc[gi][1]))));
            acc[gi][2] = fmaf(v0, w0.z, fmaf(v1, w1.z, fmaf(v2, w2.z, fmaf(v3, w3.z, acc[gi][2]))));
            acc[gi][3] = fmaf(v0, w0.w, fmaf(v1, w1.w, fmaf(v2, w2.w, fmaf(v3, w3.w, acc[gi][3]))));
        }
    }

    __shared__ float sred[8][8][4];           // warp, graph, class
    #pragma unroll
    for (int gi = 0; gi < 8; gi++) {
        float a0 = acc[gi][0], a1 = acc[gi][1], a2 = acc[gi][2], a3 = acc[gi][3];
        #pragma unroll
        for (int off = 16; off > 0; off >>= 1) {
            a0 += __shfl_xor_sync(0xffffffffu, a0, off);
            a1 += __shfl_xor_sync(0xffffffffu, a1, off);
            a2 += __shfl_xor_sync(0xffffffffu, a2, off);
            a3 += __shfl_xor_sync(0xffffffffu, a3, off);
        }
        if (lane == 0) {
            sred[warp][gi][0] = a0; sred[warp][gi][1] = a1;
            sred[warp][gi][2] = a2; sred[warp][gi][3] = a3;
        }
    }
    __syncthreads();
    if (tid < 8) {
        float l[4];
        #pragma unroll
        for (int c = 0; c < 4; c++) {
            float s = bfc[c];
            #pragma unroll
            for (int w = 0; w < 8; w++) s += sred[w][tid][c];
            l[c] = s;
        }
        float m = fmaxf(fmaxf(l[0], l[1]), fmaxf(l[2], l[3]));
        float e0 = __expf(l[0] - m), e1 = __expf(l[1] - m);
        float e2 = __expf(l[2] - m), e3 = __expf(l[3] - m);
        float inv = 1.0f / (e0 + e1 + e2 + e3);
        float* o = out + (size_t)(g0 + tid) * 4;
        o[0] = e0 * inv; o[1] = e1 * inv; o[2] = e2 * inv; o[3] = e3 * inv;
    }
}

// ---------------- launch ----------------
extern "C" void kernel_launch(void* const* d_in, const int* in_sizes, int n_in,
                              void* d_out, int out_size) {
    const float* x   = (const float*)d_in[0];
    const int*   ei  = (const int*)d_in[1];
    const float* ew  = (const float*)d_in[2];
    const float* W1  = (const float*)d_in[3];
    const float* b1  = (const float*)d_in[4];
    const float* W2  = (const float*)d_in[5];
    const float* b2  = (const float*)d_in[6];
    const float* Wfc = (const float*)d_in[7];
    const float* bfc = (const float*)d_in[8];
    float* out = (float*)d_out;

    __half* aggh; cudaGetSymbolAddress((void**)&aggh, g_aggh);
    __half* h2h;  cudaGetSymbolAddress((void**)&h2h, g_h2h);
    __half* h3h;  cudaGetSymbolAddress((void**)&h3h, g_h3h);

    const int smem12 = 26624 * 4;   // 104 KB
    cudaFuncSetAttribute(gemm12, cudaFuncAttributeMaxDynamicSharedMemorySize, smem12);

    // CSR build
    k_init<<<NN / 256, 256>>>();                   // 0
    k_deg_hist<<<EE / 256, 256>>>(ei, ew);         // 1
    k_rowalloc<<<NN / 256, 256>>>();               // 2
    k_scatter<<<EE / 256, 256>>>(ei, ew);          // 3

    // layer 1 aggregate (fp32 gathers from x, fp16 out) -> fused double GEMM
    k_agg<false><<<NN / 8, 256>>>(x, aggh);        // 4
    gemm12<<<NN / 128, 256, smem12>>>(aggh, W1, b1, W2, h2h);   // 5

    // layer 2 aggregate (fp16 in/out), then batched FC + softmax
    k_agg<true><<<NN / 8, 256>>>(h2h, h3h);        // 6
    fc_softmax8<<<128, 256>>>(h3h, Wfc, bfc, b2, out);          // 7
}